// round 4
// baseline (speedup 1.0000x reference)
#include <cuda_runtime.h>
#include <cuda_bf16.h>
#include <cstdint>
#include <cstddef>

#define Bn 8
#define Tn 2048
#define Dn 128

// ---- scratch (static device globals; no allocations) ----
__device__ __nv_bfloat16 g_zbf[Bn * Tn * Dn];   // 4 MB
__device__ float        g_z2[Bn * Tn];          // 64 KB
__device__ double       g_part[Bn * 16 * 16];   // 2048 partials

__device__ __forceinline__ uint32_t smem_u32(const void* p) {
    uint32_t a;
    asm("{ .reg .u64 t; cvta.to.shared.u64 t, %1; cvt.u32.u64 %0, t; }"
        : "=r"(a) : "l"(p));
    return a;
}

// ============================================================
// Kernel 1: bf16 cast of z + per-row squared norms
// warp handles 2 rows (ILP=2). grid = B*T/16 x 256 thr.
// ============================================================
__global__ void __launch_bounds__(256) prep_kernel(const float* __restrict__ z) {
    const int warp = threadIdx.x >> 5, lane = threadIdx.x & 31;
    const int row0 = blockIdx.x * 16 + warp * 2;
    const float4 v0 = ((const float4*)(z + (size_t)row0 * Dn))[lane];
    const float4 v1 = ((const float4*)(z + (size_t)(row0 + 1) * Dn))[lane];

    __nv_bfloat162 a0 = __floats2bfloat162_rn(v0.x, v0.y);
    __nv_bfloat162 a1 = __floats2bfloat162_rn(v0.z, v0.w);
    __nv_bfloat162 b0 = __floats2bfloat162_rn(v1.x, v1.y);
    __nv_bfloat162 b1 = __floats2bfloat162_rn(v1.z, v1.w);
    uint2 oa, ob;
    oa.x = *reinterpret_cast<uint32_t*>(&a0);
    oa.y = *reinterpret_cast<uint32_t*>(&a1);
    ob.x = *reinterpret_cast<uint32_t*>(&b0);
    ob.y = *reinterpret_cast<uint32_t*>(&b1);
    ((uint2*)g_zbf)[(size_t)row0 * 32 + lane] = oa;
    ((uint2*)g_zbf)[(size_t)(row0 + 1) * 32 + lane] = ob;

    float s0 = v0.x * v0.x + v0.y * v0.y + v0.z * v0.z + v0.w * v0.w;
    float s1 = v1.x * v1.x + v1.y * v1.y + v1.z * v1.z + v1.w * v1.w;
    #pragma unroll
    for (int off = 16; off; off >>= 1) {
        s0 += __shfl_xor_sync(0xffffffffu, s0, off);
        s1 += __shfl_xor_sync(0xffffffffu, s1, off);
    }
    if (lane == 0) { g_z2[row0] = s0; g_z2[row0 + 1] = s1; }
}

// ============================================================
// Kernel 2: fused Gram(MMA via ldmatrix) + w + weighted reduction
// grid = (16, 16, 8) = (jt, it, b); 256 threads (8 warps, 4x2)
// ============================================================
#define SM_WSTRIDE 68   // 68 words/row: ldmatrix rows land on banks 4r (conflict-free)
#define SMEM_BYTES (2 * 128 * SM_WSTRIDE * 4 + 2 * 128 * 4)

extern __shared__ unsigned char smem_raw[];

#define LDSM_X4(r0, r1, r2, r3, a) \
    asm volatile("ldmatrix.sync.aligned.m8n8.x4.shared.b16 {%0,%1,%2,%3}, [%4];" \
                 : "=r"(r0), "=r"(r1), "=r"(r2), "=r"(r3) : "r"(a))

__global__ void __launch_bounds__(256, 2)
main_kernel(const float* __restrict__ gt, const float* __restrict__ sigma) {
    uint32_t* zi  = (uint32_t*)smem_raw;
    uint32_t* zj  = zi + 128 * SM_WSTRIDE;
    float*    z2i = (float*)(zj + 128 * SM_WSTRIDE);
    float*    z2j = z2i + 128;

    const int jt = blockIdx.x, it = blockIdx.y, b = blockIdx.z;
    const int i0 = it * 128, j0 = jt * 128;
    const int tid = threadIdx.x;
    const int warp = tid >> 5, lane = tid & 31;

    // ---- L2 prefetch of this CTA's 128KB gt tile (overlaps MMA phase) ----
    {
        const char* gbase = (const char*)gt;
        #pragma unroll
        for (int p = 0; p < 4; p++) {
            int idx = tid + p * 256;                 // 0..1023
            int r = idx >> 3, c = idx & 7;
            const char* addr = gbase +
                ((size_t)(b * Tn + i0 + r) * Tn + j0) * 8 + (size_t)c * 128;
            asm volatile("prefetch.global.L2 [%0];" :: "l"(addr));
        }
    }

    // ---- load z tiles (bf16, 16B vectors) ----
    const uint4* zsrc = (const uint4*)g_zbf;     // one row = 16 uint4
    #pragma unroll
    for (int p = 0; p < 8; p++) {
        int idx = tid + p * 256;                 // 0..2047
        int r = idx >> 4, c = idx & 15;
        uint4 vi = zsrc[(size_t)(b * Tn + i0 + r) * 16 + c];
        *((uint4*)(zi + r * SM_WSTRIDE + c * 4)) = vi;
        uint4 vj = zsrc[(size_t)(b * Tn + j0 + r) * 16 + c];
        *((uint4*)(zj + r * SM_WSTRIDE + c * 4)) = vj;
    }
    if (tid < 128) z2i[tid] = g_z2[b * Tn + i0 + tid];
    else           z2j[tid - 128] = g_z2[b * Tn + j0 + (tid - 128)];
    __syncthreads();

    // ---- Gram 128x128 via mma.sync m16n8k16 bf16, ldmatrix operands ----
    const int wm = warp & 3, wn = warp >> 2;     // 4 x 2 warp grid
    const int rowBase = wm * 32, colBase = wn * 64;
    const int gr = lane >> 2, q = lane & 3;

    // ldmatrix lane addresses (bytes, shared space)
    const uint32_t ziB = smem_u32(zi), zjB = smem_u32(zj);
    const int la = lane & 15, ha = lane >> 4;              // A: row / k-half
    uint32_t aAddr0 = ziB + (uint32_t)((rowBase + la) * SM_WSTRIDE + ha * 4) * 4;
    uint32_t aAddr1 = aAddr0 + 16 * SM_WSTRIDE * 4;
    const int gq = lane >> 3;                              // B: 4 lane-groups
    uint32_t bAddr = zjB + (uint32_t)((colBase + (gq >> 1) * 8 + (lane & 7)) * SM_WSTRIDE
                                      + (gq & 1) * 4) * 4;
    const uint32_t FN_STRIDE = 16 * SM_WSTRIDE * 4;        // fn-pair stride (16 rows)

    float acc[2][8][4];
    #pragma unroll
    for (int fm = 0; fm < 2; fm++)
        #pragma unroll
        for (int fn = 0; fn < 8; fn++)
            #pragma unroll
            for (int v = 0; v < 4; v++) acc[fm][fn][v] = 0.f;

    #pragma unroll
    for (int ks = 0; ks < 8; ks++) {
        const uint32_t ko = ks * 32;             // +8 k-words = 32B
        uint32_t a[2][4], bb[4][4];
        LDSM_X4(a[0][0], a[0][1], a[0][2], a[0][3], aAddr0 + ko);
        LDSM_X4(a[1][0], a[1][1], a[1][2], a[1][3], aAddr1 + ko);
        #pragma unroll
        for (int p = 0; p < 4; p++)
            LDSM_X4(bb[p][0], bb[p][1], bb[p][2], bb[p][3], bAddr + p * FN_STRIDE + ko);

        #pragma unroll
        for (int p = 0; p < 4; p++) {
            #pragma unroll
            for (int s = 0; s < 2; s++) {
                const int fn = 2 * p + s;
                const uint32_t b0 = bb[p][2 * s], b1 = bb[p][2 * s + 1];
                #pragma unroll
                for (int fm = 0; fm < 2; fm++) {
                    asm volatile(
                        "mma.sync.aligned.m16n8k16.row.col.f32.bf16.bf16.f32 "
                        "{%0,%1,%2,%3}, {%4,%5,%6,%7}, {%8,%9}, {%0,%1,%2,%3};"
                        : "+f"(acc[fm][fn][0]), "+f"(acc[fm][fn][1]),
                          "+f"(acc[fm][fn][2]), "+f"(acc[fm][fn][3])
                        : "r"(a[fm][0]), "r"(a[fm][1]), "r"(a[fm][2]), "r"(a[fm][3]),
                          "r"(b0), "r"(b1));
                }
            }
        }
    }

    // ---- epilogue: stream gt (L2-hot), compute w, weighted accumulate ----
    float sg0 = sigma[0], sg1 = sigma[1];
    float c0 = 1.0f / (2.0f * sg0 * sg0), c1 = 1.0f / (2.0f * sg1 * sg1);
    const float4* gt4 = (const float4*)gt;       // {g(j,0),g(j,1),g(j+1,0),g(j+1,1)}
    float sum = 0.f;

    #pragma unroll
    for (int fm = 0; fm < 2; fm++) {
        const int ri = rowBase + fm * 16 + gr;
        const float z2a = z2i[ri];
        const float z2b = z2i[ri + 8];
        const size_t base0 = (size_t)(b * Tn + i0 + ri) * Tn + j0;
        const size_t base1 = base0 + (size_t)8 * Tn;
        #pragma unroll
        for (int fn = 0; fn < 8; fn++) {
            const int jj = colBase + fn * 8 + 2 * q;   // local col (even)
            const float zj0 = z2j[jj], zj1 = z2j[jj + 1];
            const float4 gA = gt4[(base0 + jj) >> 1];
            const float4 gB = gt4[(base1 + jj) >> 1];
            const float w00 = __expf(-(gA.x * gA.x * c0 + gA.y * gA.y * c1));
            const float w01 = __expf(-(gA.z * gA.z * c0 + gA.w * gA.w * c1));
            const float w10 = __expf(-(gB.x * gB.x * c0 + gB.y * gB.y * c1));
            const float w11 = __expf(-(gB.z * gB.z * c0 + gB.w * gB.w * c1));
            sum += w00 * (z2a + zj0 - 2.f * acc[fm][fn][0]);
            sum += w01 * (z2a + zj1 - 2.f * acc[fm][fn][1]);
            sum += w10 * (z2b + zj0 - 2.f * acc[fm][fn][2]);
            sum += w11 * (z2b + zj1 - 2.f * acc[fm][fn][3]);
        }
    }

    // ---- block reduce -> per-CTA partial ----
    #pragma unroll
    for (int o = 16; o; o >>= 1) sum += __shfl_xor_sync(0xffffffffu, sum, o);
    __shared__ float wsum[8];
    if (lane == 0) wsum[warp] = sum;
    __syncthreads();
    if (tid == 0) {
        float t = 0.f;
        #pragma unroll
        for (int w = 0; w < 8; w++) t += wsum[w];
        g_part[(b * 16 + it) * 16 + jt] = (double)t;
    }
}

// ============================================================
// Kernel 3: deterministic final reduce
// ============================================================
__global__ void reduce_kernel(float* __restrict__ out) {
    int tid = threadIdx.x;
    double s = 0.0;
    for (int i = tid; i < Bn * 16 * 16; i += 256) s += g_part[i];
    __shared__ double sh[256];
    sh[tid] = s;
    __syncthreads();
    for (int o = 128; o; o >>= 1) {
        if (tid < o) sh[tid] += sh[tid + o];
        __syncthreads();
    }
    if (tid == 0)
        out[0] = (float)(sh[0] / ((double)Bn * (double)Tn * (double)Tn));
}

// ============================================================
extern "C" void kernel_launch(void* const* d_in, const int* in_sizes, int n_in,
                              void* d_out, int out_size) {
    const float *z = nullptr, *gt = nullptr, *sg = nullptr;
    for (int i = 0; i < n_in; i++) {
        if (in_sizes[i] == Bn * Tn * Dn)      z  = (const float*)d_in[i];
        else if (in_sizes[i] == 2)            sg = (const float*)d_in[i];
        else                                  gt = (const float*)d_in[i];
    }

    cudaFuncSetAttribute(main_kernel,
                         cudaFuncAttributeMaxDynamicSharedMemorySize, SMEM_BYTES);

    prep_kernel<<<Bn * Tn / 16, 256>>>(z);
    dim3 grid(16, 16, Bn);
    main_kernel<<<grid, 256, SMEM_BYTES>>>(gt, sg);
    reduce_kernel<<<1, 256>>>((float*)d_out);
}

// round 5
// speedup vs baseline: 1.0004x; 1.0004x over previous
#include <cuda_runtime.h>
#include <cuda_bf16.h>
#include <cstdint>
#include <cstddef>

#define Bn 8
#define Tn 2048
#define Dn 128

// ---- scratch (static device globals; no allocations) ----
__device__ __nv_bfloat16 g_zbf[Bn * Tn * Dn];   // 4 MB
__device__ float        g_z2[Bn * Tn];          // 64 KB
__device__ double       g_part[Bn * 16 * 16];   // 2048 partials

__device__ __forceinline__ uint32_t smem_u32(const void* p) {
    uint32_t a;
    asm("{ .reg .u64 t; cvta.to.shared.u64 t, %1; cvt.u32.u64 %0, t; }"
        : "=r"(a) : "l"(p));
    return a;
}

// ============================================================
// Kernel 1: bf16 cast of z + per-row squared norms
// warp handles 2 rows (ILP=2). grid = B*T/16 x 256 thr.
// ============================================================
__global__ void __launch_bounds__(256) prep_kernel(const float* __restrict__ z) {
    const int warp = threadIdx.x >> 5, lane = threadIdx.x & 31;
    const int row0 = blockIdx.x * 16 + warp * 2;
    const float4 v0 = ((const float4*)(z + (size_t)row0 * Dn))[lane];
    const float4 v1 = ((const float4*)(z + (size_t)(row0 + 1) * Dn))[lane];

    __nv_bfloat162 a0 = __floats2bfloat162_rn(v0.x, v0.y);
    __nv_bfloat162 a1 = __floats2bfloat162_rn(v0.z, v0.w);
    __nv_bfloat162 b0 = __floats2bfloat162_rn(v1.x, v1.y);
    __nv_bfloat162 b1 = __floats2bfloat162_rn(v1.z, v1.w);
    uint2 oa, ob;
    oa.x = *reinterpret_cast<uint32_t*>(&a0);
    oa.y = *reinterpret_cast<uint32_t*>(&a1);
    ob.x = *reinterpret_cast<uint32_t*>(&b0);
    ob.y = *reinterpret_cast<uint32_t*>(&b1);
    ((uint2*)g_zbf)[(size_t)row0 * 32 + lane] = oa;
    ((uint2*)g_zbf)[(size_t)(row0 + 1) * 32 + lane] = ob;

    float s0 = v0.x * v0.x + v0.y * v0.y + v0.z * v0.z + v0.w * v0.w;
    float s1 = v1.x * v1.x + v1.y * v1.y + v1.z * v1.z + v1.w * v1.w;
    #pragma unroll
    for (int off = 16; off; off >>= 1) {
        s0 += __shfl_xor_sync(0xffffffffu, s0, off);
        s1 += __shfl_xor_sync(0xffffffffu, s1, off);
    }
    if (lane == 0) { g_z2[row0] = s0; g_z2[row0 + 1] = s1; }
}

// ============================================================
// Kernel 2: fused Gram(MMA via ldmatrix) + w + weighted reduction
// grid = (16, 16, 8) = (jt, it, b); 256 threads (8 warps, 4x2)
// ============================================================
#define SM_WSTRIDE 68   // 68 words/row: ldmatrix rows land on banks 4r (conflict-free)
#define SMEM_BYTES (2 * 128 * SM_WSTRIDE * 4 + 2 * 128 * 4)

extern __shared__ unsigned char smem_raw[];

#define LDSM_X4(r0, r1, r2, r3, a) \
    asm volatile("ldmatrix.sync.aligned.m8n8.x4.shared.b16 {%0,%1,%2,%3}, [%4];" \
                 : "=r"(r0), "=r"(r1), "=r"(r2), "=r"(r3) : "r"(a))

__global__ void __launch_bounds__(256, 2)
main_kernel(const float* __restrict__ gt, const float* __restrict__ sigma) {
    uint32_t* zi  = (uint32_t*)smem_raw;
    uint32_t* zj  = zi + 128 * SM_WSTRIDE;
    float*    z2i = (float*)(zj + 128 * SM_WSTRIDE);
    float*    z2j = z2i + 128;

    const int jt = blockIdx.x, it = blockIdx.y, b = blockIdx.z;
    const int i0 = it * 128, j0 = jt * 128;
    const int tid = threadIdx.x;
    const int warp = tid >> 5, lane = tid & 31;

    // ---- L2 prefetch of this CTA's 128KB gt tile (overlaps MMA phase) ----
    {
        const char* gbase = (const char*)gt;
        #pragma unroll
        for (int p = 0; p < 4; p++) {
            int idx = tid + p * 256;                 // 0..1023
            int r = idx >> 3, c = idx & 7;
            const char* addr = gbase +
                ((size_t)(b * Tn + i0 + r) * Tn + j0) * 8 + (size_t)c * 128;
            asm volatile("prefetch.global.L2 [%0];" :: "l"(addr));
        }
    }

    // ---- load z tiles (bf16, 16B vectors) ----
    const uint4* zsrc = (const uint4*)g_zbf;     // one row = 16 uint4
    #pragma unroll
    for (int p = 0; p < 8; p++) {
        int idx = tid + p * 256;                 // 0..2047
        int r = idx >> 4, c = idx & 15;
        uint4 vi = zsrc[(size_t)(b * Tn + i0 + r) * 16 + c];
        *((uint4*)(zi + r * SM_WSTRIDE + c * 4)) = vi;
        uint4 vj = zsrc[(size_t)(b * Tn + j0 + r) * 16 + c];
        *((uint4*)(zj + r * SM_WSTRIDE + c * 4)) = vj;
    }
    if (tid < 128) z2i[tid] = g_z2[b * Tn + i0 + tid];
    else           z2j[tid - 128] = g_z2[b * Tn + j0 + (tid - 128)];
    __syncthreads();

    // ---- Gram 128x128 via mma.sync m16n8k16 bf16, ldmatrix operands ----
    const int wm = warp & 3, wn = warp >> 2;     // 4 x 2 warp grid
    const int rowBase = wm * 32, colBase = wn * 64;
    const int gr = lane >> 2, q = lane & 3;

    // ldmatrix lane addresses (bytes, shared space)
    const uint32_t ziB = smem_u32(zi), zjB = smem_u32(zj);
    const int la = lane & 15, ha = lane >> 4;              // A: row / k-half
    uint32_t aAddr0 = ziB + (uint32_t)((rowBase + la) * SM_WSTRIDE + ha * 4) * 4;
    uint32_t aAddr1 = aAddr0 + 16 * SM_WSTRIDE * 4;
    const int gq = lane >> 3;                              // B: 4 lane-groups
    uint32_t bAddr = zjB + (uint32_t)((colBase + (gq >> 1) * 8 + (lane & 7)) * SM_WSTRIDE
                                      + (gq & 1) * 4) * 4;
    const uint32_t FN_STRIDE = 16 * SM_WSTRIDE * 4;        // fn-pair stride (16 rows)

    float acc[2][8][4];
    #pragma unroll
    for (int fm = 0; fm < 2; fm++)
        #pragma unroll
        for (int fn = 0; fn < 8; fn++)
            #pragma unroll
            for (int v = 0; v < 4; v++) acc[fm][fn][v] = 0.f;

    #pragma unroll
    for (int ks = 0; ks < 8; ks++) {
        const uint32_t ko = ks * 32;             // +8 k-words = 32B
        uint32_t a[2][4], bb[4][4];
        LDSM_X4(a[0][0], a[0][1], a[0][2], a[0][3], aAddr0 + ko);
        LDSM_X4(a[1][0], a[1][1], a[1][2], a[1][3], aAddr1 + ko);
        #pragma unroll
        for (int p = 0; p < 4; p++)
            LDSM_X4(bb[p][0], bb[p][1], bb[p][2], bb[p][3], bAddr + p * FN_STRIDE + ko);

        #pragma unroll
        for (int p = 0; p < 4; p++) {
            #pragma unroll
            for (int s = 0; s < 2; s++) {
                const int fn = 2 * p + s;
                const uint32_t b0 = bb[p][2 * s], b1 = bb[p][2 * s + 1];
                #pragma unroll
                for (int fm = 0; fm < 2; fm++) {
                    asm volatile(
                        "mma.sync.aligned.m16n8k16.row.col.f32.bf16.bf16.f32 "
                        "{%0,%1,%2,%3}, {%4,%5,%6,%7}, {%8,%9}, {%0,%1,%2,%3};"
                        : "+f"(acc[fm][fn][0]), "+f"(acc[fm][fn][1]),
                          "+f"(acc[fm][fn][2]), "+f"(acc[fm][fn][3])
                        : "r"(a[fm][0]), "r"(a[fm][1]), "r"(a[fm][2]), "r"(a[fm][3]),
                          "r"(b0), "r"(b1));
                }
            }
        }
    }

    // ---- epilogue: stream gt (L2-hot), compute w, weighted accumulate ----
    float sg0 = sigma[0], sg1 = sigma[1];
    float c0 = 1.0f / (2.0f * sg0 * sg0), c1 = 1.0f / (2.0f * sg1 * sg1);
    const float4* gt4 = (const float4*)gt;       // {g(j,0),g(j,1),g(j+1,0),g(j+1,1)}
    float sum = 0.f;

    #pragma unroll
    for (int fm = 0; fm < 2; fm++) {
        const int ri = rowBase + fm * 16 + gr;
        const float z2a = z2i[ri];
        const float z2b = z2i[ri + 8];
        const size_t base0 = (size_t)(b * Tn + i0 + ri) * Tn + j0;
        const size_t base1 = base0 + (size_t)8 * Tn;
        #pragma unroll
        for (int fn = 0; fn < 8; fn++) {
            const int jj = colBase + fn * 8 + 2 * q;   // local col (even)
            const float zj0 = z2j[jj], zj1 = z2j[jj + 1];
            const float4 gA = gt4[(base0 + jj) >> 1];
            const float4 gB = gt4[(base1 + jj) >> 1];
            const float w00 = __expf(-(gA.x * gA.x * c0 + gA.y * gA.y * c1));
            const float w01 = __expf(-(gA.z * gA.z * c0 + gA.w * gA.w * c1));
            const float w10 = __expf(-(gB.x * gB.x * c0 + gB.y * gB.y * c1));
            const float w11 = __expf(-(gB.z * gB.z * c0 + gB.w * gB.w * c1));
            sum += w00 * (z2a + zj0 - 2.f * acc[fm][fn][0]);
            sum += w01 * (z2a + zj1 - 2.f * acc[fm][fn][1]);
            sum += w10 * (z2b + zj0 - 2.f * acc[fm][fn][2]);
            sum += w11 * (z2b + zj1 - 2.f * acc[fm][fn][3]);
        }
    }

    // ---- block reduce -> per-CTA partial ----
    #pragma unroll
    for (int o = 16; o; o >>= 1) sum += __shfl_xor_sync(0xffffffffu, sum, o);
    __shared__ float wsum[8];
    if (lane == 0) wsum[warp] = sum;
    __syncthreads();
    if (tid == 0) {
        float t = 0.f;
        #pragma unroll
        for (int w = 0; w < 8; w++) t += wsum[w];
        g_part[(b * 16 + it) * 16 + jt] = (double)t;
    }
}

// ============================================================
// Kernel 3: deterministic final reduce
// ============================================================
__global__ void reduce_kernel(float* __restrict__ out) {
    int tid = threadIdx.x;
    double s = 0.0;
    for (int i = tid; i < Bn * 16 * 16; i += 256) s += g_part[i];
    __shared__ double sh[256];
    sh[tid] = s;
    __syncthreads();
    for (int o = 128; o; o >>= 1) {
        if (tid < o) sh[tid] += sh[tid + o];
        __syncthreads();
    }
    if (tid == 0)
        out[0] = (float)(sh[0] / ((double)Bn * (double)Tn * (double)Tn));
}

// ============================================================
extern "C" void kernel_launch(void* const* d_in, const int* in_sizes, int n_in,
                              void* d_out, int out_size) {
    const float *z = nullptr, *gt = nullptr, *sg = nullptr;
    for (int i = 0; i < n_in; i++) {
        if (in_sizes[i] == Bn * Tn * Dn)      z  = (const float*)d_in[i];
        else if (in_sizes[i] == 2)            sg = (const float*)d_in[i];
        else                                  gt = (const float*)d_in[i];
    }

    cudaFuncSetAttribute(main_kernel,
                         cudaFuncAttributeMaxDynamicSharedMemorySize, SMEM_BYTES);

    prep_kernel<<<Bn * Tn / 16, 256>>>(z);
    dim3 grid(16, 16, Bn);
    main_kernel<<<grid, 256, SMEM_BYTES>>>(gt, sg);
    reduce_kernel<<<1, 256>>>((float*)d_out);
}